// round 4
// baseline (speedup 1.0000x reference)
#include <cuda_runtime.h>

// Lifting wavelet forward transform, v4: barrier-free streaming, 8 pairs/thread,
// taps as kernel args (no constant-memcpy graph nodes).
// input: (4096, 8192) f32. even = in[:, ::2], odd = in[:, 1::2] (4096 each).
// wavelet[j] = scaling_rec[7-j] * (j odd ? -1 : +1)
// odd_out[k]  = odd[k]  - sum_j wavelet[j] * even[(k-j) mod 4096]
// even_out[k] = even[k] - sum_j scaling[j] * odd[(k-j) mod 4096]
// Output: [even_updated | odd_updated], each 4096x4096 f32.

#define ROWS    4096
#define ROWLEN  8192
#define HALF    4096
#define NTH     256
#define FMASK   (ROWLEN - 1)

__global__ __launch_bounds__(NTH)
void wavelet_fwd_v4(const float* __restrict__ in,
                    const float* __restrict__ scaling,
                    const float* __restrict__ scaling_rec,
                    float* __restrict__ out)
{
    const int g   = blockIdx.x * NTH + threadIdx.x;   // 0 .. 2M-1
    const int row = g >> 9;                            // 512 threads per row
    const int lk  = (g & 511) << 3;                    // pair base: 0..4088

    const float* rowp = in + (size_t)row * ROWLEN;

    // Window: input floats (2*lk - 16 + i) mod 8192, i = 0..31.
    // 8 aligned float4 loads, circular via & FMASK. Front-batched -> MLP=8.
    float wnd[32];
#pragma unroll
    for (int q = 0; q < 8; q++) {
        int fi = (2 * lk - 16 + 4 * q) & FMASK;
        float4 v = *reinterpret_cast<const float4*>(rowp + fi);
        wnd[4*q+0] = v.x; wnd[4*q+1] = v.y; wnd[4*q+2] = v.z; wnd[4*q+3] = v.w;
    }

    // Taps: uniform broadcast loads (2 lines total, L1-resident).
    float4 s0 = *reinterpret_cast<const float4*>(scaling);
    float4 s1 = *reinterpret_cast<const float4*>(scaling + 4);
    float4 r0 = *reinterpret_cast<const float4*>(scaling_rec);
    float4 r1 = *reinterpret_cast<const float4*>(scaling_rec + 4);
    const float c0 = s0.x, c1 = s0.y, c2 = s0.z, c3 = s0.w;
    const float c4 = s1.x, c5 = s1.y, c6 = s1.z, c7 = s1.w;
    const float w0 =  r1.w, w1 = -r1.z, w2 =  r1.y, w3 = -r1.x;
    const float w4 =  r0.w, w5 = -r0.z, w6 =  r0.y, w7 = -r0.x;

    // Pair (lk+m): even = wnd[2m+16], odd = wnd[2m+17].
    float rE[8], rO[8];
#pragma unroll
    for (int m = 0; m < 8; m++) {
        const int b = 2 * m + 16;
        float e8 = wnd[b], o8 = wnd[b + 1];
        float ce = w0*e8
                 + w1*wnd[b-2]  + w2*wnd[b-4]  + w3*wnd[b-6]
                 + w4*wnd[b-8]  + w5*wnd[b-10] + w6*wnd[b-12]
                 + w7*wnd[b-14];
        float co = c0*o8
                 + c1*wnd[b-1]  + c2*wnd[b-3]  + c3*wnd[b-5]
                 + c4*wnd[b-7]  + c5*wnd[b-9]  + c6*wnd[b-11]
                 + c7*wnd[b-13];
        rO[m] = o8 - ce;   // odd  - conv(even, wavelet)
        rE[m] = e8 - co;   // even - conv(odd,  scaling)
    }

    const size_t obase = (size_t)row * HALF + lk;
    float4* pe = reinterpret_cast<float4*>(out + obase);
    float4* po = reinterpret_cast<float4*>(out + (size_t)ROWS * HALF + obase);
    pe[0] = make_float4(rE[0], rE[1], rE[2], rE[3]);
    pe[1] = make_float4(rE[4], rE[5], rE[6], rE[7]);
    po[0] = make_float4(rO[0], rO[1], rO[2], rO[3]);
    po[1] = make_float4(rO[4], rO[5], rO[6], rO[7]);
}

extern "C" void kernel_launch(void* const* d_in, const int* in_sizes, int n_in,
                              void* d_out, int out_size)
{
    const float* input       = (const float*)d_in[0];
    const float* scaling     = (const float*)d_in[1];
    const float* scaling_rec = (const float*)d_in[2];
    float* out = (float*)d_out;

    const int total_threads = ROWS * (HALF / 8);       // 2M
    wavelet_fwd_v4<<<total_threads / NTH, NTH>>>(input, scaling, scaling_rec, out);
}

// round 5
// speedup vs baseline: 1.6293x; 1.6293x over previous
#include <cuda_runtime.h>

// Lifting wavelet forward transform, v5: barrier-free streaming, 8 pairs/thread,
// taps as kernel args, register cap lifted via __launch_bounds__(256, 3)
// (v4's regression was ptxas spilling the 32-float window at 40 regs).
// input: (4096, 8192) f32. even = in[:, ::2], odd = in[:, 1::2] (4096 each).
// wavelet[j] = scaling_rec[7-j] * (j odd ? -1 : +1)
// odd_out[k]  = odd[k]  - sum_j wavelet[j] * even[(k-j) mod 4096]
// even_out[k] = even[k] - sum_j scaling[j] * odd[(k-j) mod 4096]
// Output: [even_updated | odd_updated], each 4096x4096 f32.

#define ROWS    4096
#define ROWLEN  8192
#define HALF    4096
#define NTH     256
#define FMASK   (ROWLEN - 1)

__global__ __launch_bounds__(NTH, 3)   // <= 85 regs/thread: window stays in regs
void wavelet_fwd_v5(const float* __restrict__ in,
                    const float* __restrict__ scaling,
                    const float* __restrict__ scaling_rec,
                    float* __restrict__ out)
{
    const int g   = blockIdx.x * NTH + threadIdx.x;   // 0 .. 2M-1
    const int row = g >> 9;                            // 512 threads per row
    const int lk  = (g & 511) << 3;                    // pair base: 0..4088

    const float* rowp = in + (size_t)row * ROWLEN;

    // Window: input floats (2*lk - 16 + i) mod 8192, i = 0..31.
    // 8 aligned float4 loads, circular via & FMASK. Front-batched -> MLP=8.
    float wnd[32];
#pragma unroll
    for (int q = 0; q < 8; q++) {
        int fi = (2 * lk - 16 + 4 * q) & FMASK;
        float4 v = *reinterpret_cast<const float4*>(rowp + fi);
        wnd[4*q+0] = v.x; wnd[4*q+1] = v.y; wnd[4*q+2] = v.z; wnd[4*q+3] = v.w;
    }

    // Taps: uniform broadcast loads (2 lines total, L1-resident).
    float4 s0 = *reinterpret_cast<const float4*>(scaling);
    float4 s1 = *reinterpret_cast<const float4*>(scaling + 4);
    float4 r0 = *reinterpret_cast<const float4*>(scaling_rec);
    float4 r1 = *reinterpret_cast<const float4*>(scaling_rec + 4);
    const float c0 = s0.x, c1 = s0.y, c2 = s0.z, c3 = s0.w;
    const float c4 = s1.x, c5 = s1.y, c6 = s1.z, c7 = s1.w;
    const float w0 =  r1.w, w1 = -r1.z, w2 =  r1.y, w3 = -r1.x;
    const float w4 =  r0.w, w5 = -r0.z, w6 =  r0.y, w7 = -r0.x;

    // Pair (lk+m): even = wnd[2m+16], odd = wnd[2m+17].
    float rE[8], rO[8];
#pragma unroll
    for (int m = 0; m < 8; m++) {
        const int b = 2 * m + 16;
        float e8 = wnd[b], o8 = wnd[b + 1];
        float ce = w0*e8
                 + w1*wnd[b-2]  + w2*wnd[b-4]  + w3*wnd[b-6]
                 + w4*wnd[b-8]  + w5*wnd[b-10] + w6*wnd[b-12]
                 + w7*wnd[b-14];
        float co = c0*o8
                 + c1*wnd[b-1]  + c2*wnd[b-3]  + c3*wnd[b-5]
                 + c4*wnd[b-7]  + c5*wnd[b-9]  + c6*wnd[b-11]
                 + c7*wnd[b-13];
        rO[m] = o8 - ce;   // odd  - conv(even, wavelet)
        rE[m] = e8 - co;   // even - conv(odd,  scaling)
    }

    const size_t obase = (size_t)row * HALF + lk;
    float4* pe = reinterpret_cast<float4*>(out + obase);
    float4* po = reinterpret_cast<float4*>(out + (size_t)ROWS * HALF + obase);
    pe[0] = make_float4(rE[0], rE[1], rE[2], rE[3]);
    pe[1] = make_float4(rE[4], rE[5], rE[6], rE[7]);
    po[0] = make_float4(rO[0], rO[1], rO[2], rO[3]);
    po[1] = make_float4(rO[4], rO[5], rO[6], rO[7]);
}

extern "C" void kernel_launch(void* const* d_in, const int* in_sizes, int n_in,
                              void* d_out, int out_size)
{
    const float* input       = (const float*)d_in[0];
    const float* scaling     = (const float*)d_in[1];
    const float* scaling_rec = (const float*)d_in[2];
    float* out = (float*)d_out;

    const int total_threads = ROWS * (HALF / 8);       // 2M
    wavelet_fwd_v5<<<total_threads / NTH, NTH>>>(input, scaling, scaling_rec, out);
}

// round 6
// speedup vs baseline: 1.7044x; 1.0461x over previous
#include <cuda_runtime.h>

// Lifting wavelet forward transform, v6 = v3 body (best kernel: 37.5us) with
// taps read from kernel args instead of __constant__ (kills the two
// cudaMemcpyToSymbolAsync graph nodes that cost ~10us of total time).
// input: (4096, 8192) f32. even = in[:, ::2], odd = in[:, 1::2] (4096 each).
// wavelet[j] = scaling_rec[7-j] * (j odd ? -1 : +1)
// odd_out[k]  = odd[k]  - sum_j wavelet[j] * even[(k-j) mod 4096]
// even_out[k] = even[k] - sum_j scaling[j] * odd[(k-j) mod 4096]
// Output: [even_updated | odd_updated], each 4096x4096 f32.

#define ROWS    4096
#define ROWLEN  8192
#define HALF    4096
#define NTH     256
#define FMASK   (ROWLEN - 1)

__global__ __launch_bounds__(NTH)
void wavelet_fwd_v6(const float* __restrict__ in,
                    const float* __restrict__ scaling,
                    const float* __restrict__ scaling_rec,
                    float* __restrict__ out)
{
    const int g   = blockIdx.x * NTH + threadIdx.x;  // 0 .. 4M-1
    const int row = g >> 10;                          // 1024 threads per row
    const int lk  = (g & 1023) << 2;                  // pair base: 0..4092

    const float* rowp = in + (size_t)row * ROWLEN;

    // Window: input floats (2*lk - 16 + i) mod 8192, i = 0..23.
    // 6 aligned float4 loads, circular via & FMASK. Front-batched -> MLP=6.
    float wnd[24];
#pragma unroll
    for (int q = 0; q < 6; q++) {
        int fi = (2 * lk - 16 + 4 * q) & FMASK;
        float4 v = *reinterpret_cast<const float4*>(rowp + fi);
        wnd[4*q+0] = v.x; wnd[4*q+1] = v.y; wnd[4*q+2] = v.z; wnd[4*q+3] = v.w;
    }

    // Taps: warp-uniform loads, 2 cache lines total (L1/L2-resident).
    float4 s0 = *reinterpret_cast<const float4*>(scaling);
    float4 s1 = *reinterpret_cast<const float4*>(scaling + 4);
    float4 r0 = *reinterpret_cast<const float4*>(scaling_rec);
    float4 r1 = *reinterpret_cast<const float4*>(scaling_rec + 4);
    const float c0 = s0.x, c1 = s0.y, c2 = s0.z, c3 = s0.w;
    const float c4 = s1.x, c5 = s1.y, c6 = s1.z, c7 = s1.w;
    // wavelet[j] = scaling_rec[7-j] * (j odd ? -1 : +1)
    const float w0 =  r1.w, w1 = -r1.z, w2 =  r1.y, w3 = -r1.x;
    const float w4 =  r0.w, w5 = -r0.z, w6 =  r0.y, w7 = -r0.x;

    // Pair (lk+m): even = wnd[2m+16], odd = wnd[2m+17].
    float rE[4], rO[4];
#pragma unroll
    for (int m = 0; m < 4; m++) {
        const int b = 2 * m + 16;
        float e8 = wnd[b], o8 = wnd[b + 1];
        float ce = w0*e8
                 + w1*wnd[b-2]  + w2*wnd[b-4]  + w3*wnd[b-6]
                 + w4*wnd[b-8]  + w5*wnd[b-10] + w6*wnd[b-12]
                 + w7*wnd[b-14];
        float co = c0*o8
                 + c1*wnd[b-1]  + c2*wnd[b-3]  + c3*wnd[b-5]
                 + c4*wnd[b-7]  + c5*wnd[b-9]  + c6*wnd[b-11]
                 + c7*wnd[b-13];
        rO[m] = o8 - ce;   // odd  - conv(even, wavelet)
        rE[m] = e8 - co;   // even - conv(odd,  scaling)
    }

    const size_t obase = (size_t)row * HALF + lk;
    *reinterpret_cast<float4*>(out + obase) =
        make_float4(rE[0], rE[1], rE[2], rE[3]);
    *reinterpret_cast<float4*>(out + (size_t)ROWS * HALF + obase) =
        make_float4(rO[0], rO[1], rO[2], rO[3]);
}

extern "C" void kernel_launch(void* const* d_in, const int* in_sizes, int n_in,
                              void* d_out, int out_size)
{
    const float* input       = (const float*)d_in[0];
    const float* scaling     = (const float*)d_in[1];
    const float* scaling_rec = (const float*)d_in[2];
    float* out = (float*)d_out;

    const int total_threads = ROWS * (HALF / 4);       // 4M
    wavelet_fwd_v6<<<total_threads / NTH, NTH>>>(input, scaling, scaling_rec, out);
}

// round 7
// speedup vs baseline: 1.7636x; 1.0347x over previous
#include <cuda_runtime.h>

// Lifting wavelet forward transform, v7: v6 (arg taps, no graph memcpy nodes)
// with register pressure fixed: launch_bounds cap + phased tap liveness
// (wavelet taps fully consumed before scaling taps are loaded).
// input: (4096, 8192) f32. even = in[:, ::2], odd = in[:, 1::2] (4096 each).
// wavelet[j] = scaling_rec[7-j] * (j odd ? -1 : +1)
// odd_out[k]  = odd[k]  - sum_j wavelet[j] * even[(k-j) mod 4096]
// even_out[k] = even[k] - sum_j scaling[j] * odd[(k-j) mod 4096]
// Output: [even_updated | odd_updated], each 4096x4096 f32.

#define ROWS    4096
#define ROWLEN  8192
#define HALF    4096
#define NTH     256
#define FMASK   (ROWLEN - 1)

__global__ __launch_bounds__(NTH, 6)   // cap at 42 regs: window stays resident
void wavelet_fwd_v7(const float* __restrict__ in,
                    const float* __restrict__ scaling,
                    const float* __restrict__ scaling_rec,
                    float* __restrict__ out)
{
    const int g   = blockIdx.x * NTH + threadIdx.x;  // 0 .. 4M-1
    const int row = g >> 10;                          // 1024 threads per row
    const int lk  = (g & 1023) << 2;                  // pair base: 0..4092

    const float* rowp = in + (size_t)row * ROWLEN;

    // Window: input floats (2*lk - 16 + i) mod 8192, i = 0..23.
    // 6 aligned float4 loads, circular via & FMASK. Front-batched -> MLP=6.
    float wnd[24];
#pragma unroll
    for (int q = 0; q < 6; q++) {
        int fi = (2 * lk - 16 + 4 * q) & FMASK;
        float4 v = *reinterpret_cast<const float4*>(rowp + fi);
        wnd[4*q+0] = v.x; wnd[4*q+1] = v.y; wnd[4*q+2] = v.z; wnd[4*q+3] = v.w;
    }

    float rE[4], rO[4];

    // --- Phase 1: wavelet taps only (8 live tap regs), produce rO. ---
    {
        float4 r0 = *reinterpret_cast<const float4*>(scaling_rec);
        float4 r1 = *reinterpret_cast<const float4*>(scaling_rec + 4);
        // wavelet[j] = scaling_rec[7-j] * (j odd ? -1 : +1)
        const float w0 =  r1.w, w1 = -r1.z, w2 =  r1.y, w3 = -r1.x;
        const float w4 =  r0.w, w5 = -r0.z, w6 =  r0.y, w7 = -r0.x;
#pragma unroll
        for (int m = 0; m < 4; m++) {
            const int b = 2 * m + 16;      // even of pair (lk+m)
            float ce = w0*wnd[b]
                     + w1*wnd[b-2]  + w2*wnd[b-4]  + w3*wnd[b-6]
                     + w4*wnd[b-8]  + w5*wnd[b-10] + w6*wnd[b-12]
                     + w7*wnd[b-14];
            rO[m] = wnd[b + 1] - ce;       // odd - conv(even, wavelet)
        }
    }

    // --- Phase 2: scaling taps only, produce rE. ---
    {
        float4 s0 = *reinterpret_cast<const float4*>(scaling);
        float4 s1 = *reinterpret_cast<const float4*>(scaling + 4);
        const float c0 = s0.x, c1 = s0.y, c2 = s0.z, c3 = s0.w;
        const float c4 = s1.x, c5 = s1.y, c6 = s1.z, c7 = s1.w;
#pragma unroll
        for (int m = 0; m < 4; m++) {
            const int b = 2 * m + 16;
            float co = c0*wnd[b+1]
                     + c1*wnd[b-1]  + c2*wnd[b-3]  + c3*wnd[b-5]
                     + c4*wnd[b-7]  + c5*wnd[b-9]  + c6*wnd[b-11]
                     + c7*wnd[b-13];
            rE[m] = wnd[b] - co;           // even - conv(odd, scaling)
        }
    }

    const size_t obase = (size_t)row * HALF + lk;
    *reinterpret_cast<float4*>(out + obase) =
        make_float4(rE[0], rE[1], rE[2], rE[3]);
    *reinterpret_cast<float4*>(out + (size_t)ROWS * HALF + obase) =
        make_float4(rO[0], rO[1], rO[2], rO[3]);
}

extern "C" void kernel_launch(void* const* d_in, const int* in_sizes, int n_in,
                              void* d_out, int out_size)
{
    const float* input       = (const float*)d_in[0];
    const float* scaling     = (const float*)d_in[1];
    const float* scaling_rec = (const float*)d_in[2];
    float* out = (float*)d_out;

    const int total_threads = ROWS * (HALF / 4);       // 4M
    wavelet_fwd_v7<<<total_threads / NTH, NTH>>>(input, scaling, scaling_rec, out);
}